// round 9
// baseline (speedup 1.0000x reference)
#include <cuda_runtime.h>
#include <cstdint>

#define B_  8
#define H_  224
#define W_  224
#define C_  192
#define QT  8        // q positions per block
#define NQ  2        // q per thread
#define PAIRS 32     // channel pairs (threadIdx.x)
#define QTH  4       // warps (threadIdx.y), each owns 2 q positions
#define NTHREADS 128
#define RH  56       // output rows per block
#define WCOLS 8      // staged columns per warp (private window)
#define STAGES 6
#define WARP_REGION 2048                      // 8 cols * 64 ch * 4 B
#define STAGE_BYTES (4 * WARP_REGION)         // 8192 B per stage (4 warps)
#define RING_BYTES  (STAGES * STAGE_BYTES)    // 49152 B
#define ROWSZ (W_ * C_)
#define IMGSZ (H_ * W_ * C_)

typedef unsigned long long u64;

__device__ __forceinline__ void fma2(u64 &d, u64 a, u64 b) {
    asm("fma.rn.f32x2 %0, %1, %2, %0;" : "+l"(d) : "l"(a), "l"(b));
}
__device__ __forceinline__ u64 pack2(float lo, float hi) {
    return (u64)__float_as_uint(lo) | ((u64)__float_as_uint(hi) << 32);
}
__device__ __forceinline__ void cpasync16(uint32_t dst, const float* src) {
    asm volatile("cp.async.cg.shared.global [%0], [%1], 16;" :: "r"(dst), "l"(src));
}
__device__ __forceinline__ void cp_commit() {
    asm volatile("cp.async.commit_group;" ::: "memory");
}
__device__ __forceinline__ void cp_wait2() {
    asm volatile("cp.async.wait_group 2;" ::: "memory");
}
__device__ __forceinline__ void cp_wait0() {
    asm volatile("cp.async.wait_group 0;" ::: "memory");
}
__device__ __forceinline__ uint32_t smem_u32(const void* p) {
    uint32_t a;
    asm("{ .reg .u64 t; cvta.to.shared.u64 t, %1; cvt.u32.u64 %0, t; }" : "=r"(a) : "l"(p));
    return a;
}

// Stage one input row into THIS WARP's private region of ring stage offP.
// 4 cp.async.16 per lane (8 cols x 16 float4 = 128 float4 / 32 lanes).
#define STAGE_ROW() do {                                                      \
    cpasync16(sdst0 + offP, rowPtr + colG0);                                  \
    cpasync16(sdst1 + offP, rowPtr + colG1);                                  \
    cpasync16(sdst2 + offP, rowPtr + colG2);                                  \
    cpasync16(sdst3 + offP, rowPtr + colG3);                                  \
    rowPtr += ROWSZ; if (rowPtr >= xEnd) rowPtr -= IMGSZ;                     \
    offP += STAGE_BYTES; if (offP >= RING_BYTES) offP -= RING_BYTES;          \
} while (0)

// Compute half-step at row phase T7 (t % 7), consuming this warp's region of
// the stage at offC. Kernel rows i in [ILO, IHI] only (wedge pruning).
#define STEP_RANGE(T7, ILO, IHI, DOSTORE) do {                                \
    const char* sb = (const char*)sbuf + offC + ty * WARP_REGION + tx * 8;    \
    u64 w[8];                                                                 \
    _Pragma("unroll")                                                         \
    for (int d = 0; d < 8; ++d)                                               \
        w[d] = *(const u64*)(sb + d * 256);                                   \
    _Pragma("unroll")                                                         \
    for (int i = 0; i < 7; ++i) {                                             \
        if (i >= (ILO) && i <= (IHI)) {                                       \
            const int s = ((T7) + i + 2) % 7;                                 \
            _Pragma("unroll")                                                 \
            for (int j = 0; j < 7; ++j) {                                     \
                const u64 kv = kreg[i * 7 + j];                               \
                fma2(acc[s][0], kv, w[6 - j]);                                \
                fma2(acc[s][1], kv, w[7 - j]);                                \
            }                                                                 \
        }                                                                     \
    }                                                                         \
    {                                                                         \
        const int so = ((T7) + 2) % 7;                                        \
        if (DOSTORE) {                                                        \
            *(u64*)(out + outOff)      = acc[so][0];                          \
            *(u64*)(out + outOff + C_) = acc[so][1];                          \
            outOff += ROWSZ;                                                  \
        }                                                                     \
        acc[so][0] = 0ULL; acc[so][1] = 0ULL;                                 \
    }                                                                         \
    offC += STAGE_BYTES; if (offC >= RING_BYTES) offC -= RING_BYTES;          \
} while (0)

// Warp-private macro: 2 rows, NO __syncthreads.
// Prefetch rows 2m+4, 2m+5 (overwrites stages consumed at macro m-1: safe by
// in-order issue -- those FMAs already issued), one commit group, wait <= 2
// groups (=> rows 2m, 2m+1 landed), __syncwarp for cross-lane visibility.
#define MACRO2W(T7a, LOa, STa, T7b, LOb, STb) do {                            \
    STAGE_ROW();                                                              \
    STAGE_ROW();                                                              \
    cp_commit();                                                              \
    cp_wait2();                                                               \
    __syncwarp();                                                             \
    STEP_RANGE(T7a, LOa, 6, STa);                                             \
    STEP_RANGE(T7b, LOb, 6, STb);                                             \
} while (0)

// 7 macros = 14 rows (acc-phase period); ring phase carried by offC/offP.
#define GROUP7M()                                                             \
    MACRO2W(6, 0, 1, 0, 0, 1); MACRO2W(1, 0, 1, 2, 0, 1);                     \
    MACRO2W(3, 0, 1, 4, 0, 1); MACRO2W(5, 0, 1, 6, 0, 1);                     \
    MACRO2W(0, 0, 1, 1, 0, 1); MACRO2W(2, 0, 1, 3, 0, 1);                     \
    MACRO2W(4, 0, 1, 5, 0, 1)

__global__ void __launch_bounds__(NTHREADS, 3)
dwconv_warp(const float* __restrict__ x, const float* __restrict__ kern,
            float* __restrict__ out)
{
    __shared__ float sbuf[STAGES][4][WCOLS][64];   // 49,152 B, warp-private regions

    const int tx = threadIdx.x;             // channel pair 0..31 (= lane)
    const int ty = threadIdx.y;             // warp 0..3

    const int wt = blockIdx.x;              // 0..27
    const int ht = blockIdx.y;              // 0..3
    const int bz = blockIdx.z;              // 0..23
    const int b  = bz / 3;
    const int g  = bz % 3;

    const int qbase = wt * QT;
    const int p0    = ht * RH;              // p0 % 7 == 0
    const int cbase = g * 64;
    const int c0    = cbase + 2 * tx;

    // ---- 49 kernel taps for this channel pair -> registers (f32x2) ----
    u64 kreg[49];
    #pragma unroll
    for (int t = 0; t < 49; ++t)
        kreg[t] = pack2(kern[c0 * 49 + t], kern[(c0 + 1) * 49 + t]);

    // ---- warp-private staging plan: lane handles float4 idx lane+32k ----
    // col-in-window sc_k = (lane>>4) + 2k, v = lane & 15
    const int scB = tx >> 4;                // 0 or 1
    const int v   = tx & 15;
    int colG0, colG1, colG2, colG3;
    {
        int qw = qbase - 3 + 2 * ty;        // warp window start (global q)
        #define MKCOL(K, DST) do {                                            \
            int q = qw + scB + 2 * (K);                                       \
            q += (q < 0) ? W_ : 0; q -= (q >= W_) ? W_ : 0;                   \
            DST = q * C_ + cbase + v * 4;                                     \
        } while (0)
        MKCOL(0, colG0); MKCOL(1, colG1); MKCOL(2, colG2); MKCOL(3, colG3);
        #undef MKCOL
    }
    const uint32_t sbase = smem_u32(&sbuf[0][0][0][0])
                         + (uint32_t)(ty * WARP_REGION + v * 16);
    const uint32_t sdst0 = sbase + (scB + 0) * 256;
    const uint32_t sdst1 = sbase + (scB + 2) * 256;
    const uint32_t sdst2 = sbase + (scB + 4) * 256;
    const uint32_t sdst3 = sbase + (scB + 6) * 256;

    // row cursor (circular over H, pointer-only)
    const float* const xBase = x + b * IMGSZ;
    const float* const xEnd  = xBase + IMGSZ;
    const float* rowPtr = xBase + (p0 - 3 < 0 ? p0 - 3 + H_ : p0 - 3) * ROWSZ;

    uint32_t offP = 0;                      // prefetch cursor
    uint32_t offC = 0;                      // consume cursor

    // ---- prologue: stage rows 0..3 as two commit groups ----
    STAGE_ROW(); STAGE_ROW(); cp_commit();  // G0: rows 0,1 -> stages 0,1
    STAGE_ROW(); STAGE_ROW(); cp_commit();  // G1: rows 2,3 -> stages 2,3

    // 7 rolling accumulators (static slots), f32x2 x NQ
    u64 acc[7][2];
    #pragma unroll
    for (int m = 0; m < 7; ++m) { acc[m][0] = 0ULL; acc[m][1] = 0ULL; }

    const int qOut = qbase + ty * NQ;
    int outOff = ((b * H_ + p0) * W_ + qOut) * C_ + c0;

    // ---- warm-up: rows 0..5, wedge-pruned (i >= 6-t), no stores ----
    MACRO2W(0, 6, 0, 1, 5, 0);
    MACRO2W(2, 4, 0, 3, 3, 0);
    MACRO2W(4, 2, 0, 5, 1, 0);

    // ---- main: rows 6..47, three 7-macro groups ----
    #pragma unroll 1
    for (int o = 0; o < 3; ++o) {
        GROUP7M();
    }
    // ---- remainder: rows 48..55 (prefetching rows 52..59) ----
    MACRO2W(6, 0, 1, 0, 0, 1);
    MACRO2W(1, 0, 1, 2, 0, 1);
    MACRO2W(3, 0, 1, 4, 0, 1);
    MACRO2W(5, 0, 1, 6, 0, 1);

    // ---- stage rows 60,61 (stages of rows 54,55: consumed last macro) ----
    STAGE_ROW(); STAGE_ROW(); cp_commit();

    // ---- tail: rows 56..61, wedge-pruned (i <= 61-t), all staged ----
    cp_wait0();
    __syncwarp();
    STEP_RANGE(0, 0, 5, 1);
    STEP_RANGE(1, 0, 4, 1);
    STEP_RANGE(2, 0, 3, 1);
    STEP_RANGE(3, 0, 2, 1);
    STEP_RANGE(4, 0, 1, 1);
    STEP_RANGE(5, 0, 0, 1);
}

extern "C" void kernel_launch(void* const* d_in, const int* in_sizes, int n_in,
                              void* d_out, int out_size) {
    const float* x    = (const float*)d_in[0];   // (8,224,224,192) fp32
    const float* kern = (const float*)d_in[1];   // (192,7,7) fp32
    float* out        = (float*)d_out;           // (8,224,224,192) fp32

    dim3 grid(W_ / QT, H_ / RH, B_ * 3);  // 28 x 4 x 24 = 2688 blocks
    dim3 block(PAIRS, QTH, 1);            // 128 threads
    dwconv_warp<<<grid, block>>>(x, kern, out);
}